// round 6
// baseline (speedup 1.0000x reference)
#include <cuda_runtime.h>
#include <cuda_bf16.h>

#define BATCH   16384
#define EMBED   64
#define N_EDGES 524288
#define FULL    0xffffffffu
#define NBLK    444          // 3 CTAs/SM x 148 SMs — all resident
#define NTHR    256
#define NWARPS  (NBLK * NTHR / 32)

// Scratch (device globals — no allocation allowed)
__device__ float g_acc[BATCH * EMBED];   // 4 MB segment sums
__device__ float g_cnt[BATCH];           // segment counts
__device__ int   g_bar[2];               // grid barrier counters
__device__ int   g_done;                 // end-of-kernel reset counter

// ---------------------------------------------------------------------------
// Grid barrier: safe because all NBLK blocks are co-resident by construction.
// Counters are reset by the last-arriving block at kernel end (replay-safe).
// ---------------------------------------------------------------------------
__device__ __forceinline__ void grid_barrier(int which) {
    __syncthreads();
    if (threadIdx.x == 0) {
        __threadfence();                        // release prior writes
        atomicAdd(&g_bar[which], 1);
        while (atomicAdd(&g_bar[which], 0) < NBLK) { }
        __threadfence();                        // acquire others' writes
    }
    __syncthreads();
}

// ---------------------------------------------------------------------------
// Fused kernel: zero -> barrier -> edge aggregation -> barrier -> MLP
// ---------------------------------------------------------------------------
__global__ void __launch_bounds__(NTHR, 3)
fused_kernel(const int*   __restrict__ nodes,
             const int*   __restrict__ neigh_ids,
             const int*   __restrict__ seg_ids,
             const float* __restrict__ features,
             const float* __restrict__ w1,
             const float* __restrict__ b1,
             float*       __restrict__ out) {
    __shared__ float w1s[64 * 129];                 // padded stage of w1
    __shared__ float b1s[64];
    __shared__ __align__(16) float comb[4][128];    // 4 rows of concat
    __shared__ float part[4][64 * 5];               // stride-5 padded partials

    const int tid   = threadIdx.x;
    const int lane  = tid & 31;
    const int gtid  = blockIdx.x * NTHR + tid;
    const int gwarp = gtid >> 5;

    // ---------------- phase 0: zero accumulators + stage weights ----------
    for (int idx = tid; idx < 64 * 128; idx += NTHR) {
        const int j = idx >> 7;
        const int k = idx & 127;
        w1s[j * 129 + k] = w1[idx];                 // w1 row-major (64,128)
    }
    if (tid < 64) b1s[tid] = b1[tid];

    {
        const float4 z = make_float4(0.f, 0.f, 0.f, 0.f);
        for (int i = gtid; i < 262144; i += NBLK * NTHR)
            ((float4*)g_acc)[i] = z;
        for (int i = gtid; i < 4096; i += NBLK * NTHR)
            ((float4*)g_cnt)[i] = z;
    }

    grid_barrier(0);        // zeros visible everywhere (also covers smem stage)

    // ---------------- phase 1: edge aggregation (R2 design, persistent) ----
    {
        const float2* __restrict__ feats2 = (const float2*)features;
        for (int chunk = gwarp; chunk < N_EDGES / 32; chunk += NWARPS) {
            const int e0 = chunk * 32;
            const int my_seg = seg_ids[e0 + lane];     // coalesced
            const int my_nid = neigh_ids[e0 + lane];

            float2 acc = make_float2(0.0f, 0.0f);
            int cur = __shfl_sync(FULL, my_seg, 0);
            int runlen = 0;

            #pragma unroll
            for (int c = 0; c < 32; c += 8) {
                int    n[8], s[8];
                float2 v[8];
                #pragma unroll
                for (int u = 0; u < 8; ++u) n[u] = __shfl_sync(FULL, my_nid, c + u);
                #pragma unroll
                for (int u = 0; u < 8; ++u) v[u] = feats2[(size_t)n[u] * 32 + lane];
                #pragma unroll
                for (int u = 0; u < 8; ++u) s[u] = __shfl_sync(FULL, my_seg, c + u);
                #pragma unroll
                for (int u = 0; u < 8; ++u) {
                    if (s[u] != cur) {          // warp-uniform (s broadcast)
                        atomicAdd(&g_acc[cur * EMBED + 2 * lane],     acc.x);
                        atomicAdd(&g_acc[cur * EMBED + 2 * lane + 1], acc.y);
                        if (lane == 0) atomicAdd(&g_cnt[cur], (float)runlen);
                        acc = make_float2(0.0f, 0.0f);
                        cur = s[u];
                        runlen = 0;
                    }
                    acc.x += v[u].x;
                    acc.y += v[u].y;
                    ++runlen;
                }
            }
            atomicAdd(&g_acc[cur * EMBED + 2 * lane],     acc.x);
            atomicAdd(&g_acc[cur * EMBED + 2 * lane + 1], acc.y);
            if (lane == 0) atomicAdd(&g_cnt[cur], (float)runlen);
        }
    }

    grid_barrier(1);        // all segment sums complete

    // ---------------- phase 2: MLP (register-tiled, packed f32x2 FMA) ------
    {
        const int g = tid >> 6;                     // k-group 0..3
        const int j = tid & 63;                     // output dim

        unsigned long long w2[16];
        #pragma unroll
        for (int kk = 0; kk < 16; ++kk) {
            const float lo = w1s[j * 129 + g * 32 + 2 * kk];
            const float hi = w1s[j * 129 + g * 32 + 2 * kk + 1];
            asm("mov.b64 %0, {%1, %2};" : "=l"(w2[kk]) : "f"(lo), "f"(hi));
        }

        const int r = tid >> 6;
        for (int base = blockIdx.x * 4; base < BATCH; base += NBLK * 4) {
            {
                const int b = base + r;
                const int node = nodes[b];
                comb[r][j]      = features[(size_t)node * EMBED + j];
                const float inv = 1.0f / fmaxf(g_cnt[b], 1.0f);
                comb[r][64 + j] = g_acc[b * EMBED + j] * inv;
            }
            __syncthreads();

            #pragma unroll
            for (int rr = 0; rr < 4; ++rr) {
                const ulonglong2* c2 = (const ulonglong2*)&comb[rr][g * 32];
                unsigned long long acc = 0ull;      // packed {0.f, 0.f}
                #pragma unroll
                for (int q = 0; q < 8; ++q) {       // 8 x LDS.128 broadcast
                    const ulonglong2 c = c2[q];
                    asm("fma.rn.f32x2 %0, %1, %2, %0;"
                        : "+l"(acc) : "l"(c.x), "l"(w2[2 * q]));
                    asm("fma.rn.f32x2 %0, %1, %2, %0;"
                        : "+l"(acc) : "l"(c.y), "l"(w2[2 * q + 1]));
                }
                float lo, hi;
                asm("mov.b64 {%0, %1}, %2;" : "=f"(lo), "=f"(hi) : "l"(acc));
                part[rr][j * 5 + g] = lo + hi;      // conflict-free (5⊥32)
            }
            __syncthreads();

            {
                const int b = base + r;
                const float s = part[r][j * 5 + 0] + part[r][j * 5 + 1] +
                                part[r][j * 5 + 2] + part[r][j * 5 + 3] + b1s[j];
                out[(size_t)b * EMBED + j] = fmaxf(s, 0.0f);
            }
            __syncthreads();
        }
    }

    // ---------------- epilogue: last block resets barrier state ------------
    __syncthreads();
    if (threadIdx.x == 0) {
        const int t = atomicAdd(&g_done, 1);
        if (t == NBLK - 1) {          // everyone else has finished all barriers
            g_bar[0] = 0;
            g_bar[1] = 0;
            g_done   = 0;
            __threadfence();
        }
    }
}

// ---------------------------------------------------------------------------
// Launch — single fused kernel (no zero kernel, no inter-kernel gaps)
// inputs: nodes(i32,16384) neigh_ids(i32,524288) seg_ids(i32,524288)
//         features(f32,64M) w1(f32,8192) b1(f32,64)   output: f32 (16384,64)
// ---------------------------------------------------------------------------
extern "C" void kernel_launch(void* const* d_in, const int* in_sizes, int n_in,
                              void* d_out, int out_size) {
    const int*   nodes     = (const int*)  d_in[0];
    const int*   neigh_ids = (const int*)  d_in[1];
    const int*   seg_ids   = (const int*)  d_in[2];
    const float* features  = (const float*)d_in[3];
    const float* w1        = (const float*)d_in[4];
    const float* b1        = (const float*)d_in[5];
    float*       out       = (float*)d_out;

    fused_kernel<<<NBLK, NTHR>>>(nodes, neigh_ids, seg_ids,
                                 features, w1, b1, out);
}